// round 16
// baseline (speedup 1.0000x reference)
#include <cuda_runtime.h>
#include <cuda_bf16.h>
#include <cstdint>

// GestureClassifier: 2 stacks x 5-layer LSTM (H=32, B=16384, T=20) + FC(1280->128 relu ->5)
// v7: pair-of-warps LSTM, x-projection hoisted out of the recurrence.
//  - per layer phase 1: Wih.x_t for ALL t as pipelined mma GEMM (bias folded),
//    fp32 partials -> per-warp gmem scratch (same-thread readback, prefetched)
//  - phase 2 (recurrent): only Whh.h -> 48 hmma/step (kt 2,3), B-hi in regs,
//    B-lo in smem; h identity closes in-warp; partner half via smem + bar.sync(64)
//  - tanh.approx.f32 activations (sig via tanh identity): 5 MUFU per gate-quad

#define BB 16384
#define TT 20
#define NCTA 1024   // 2 stacks * 512 CTAs; CTA = 4 warps = 2 pairs = 32 elements
#define USE_FAST_ACT 1

typedef unsigned long long ull;
typedef uint32_t u32;

static __device__ __align__(16) ulonglong2 d_x[(size_t)NCTA * 2 * TT * 4 * 32]; // per-pair h ring
static __device__ __align__(16) float4 d_xp[(size_t)NCTA * 4 * TT * 8 * 32];    // x-proj partials
static __device__ float d_fcT[(size_t)2 * TT * 32 * BB];   // [k=0..1279][b]
static __device__ float d_wt[1280 * 128];                  // fc1_w transposed [k][o]

// ---------------- helpers ----------------
__device__ __forceinline__ u32 pkbf(float lo, float hi) {   // lo -> low 16 bits
    u32 r; asm("cvt.rn.bf16x2.f32 %0, %1, %2;" : "=r"(r) : "f"(hi), "f"(lo)); return r;
}
__device__ __forceinline__ void split2(float x0, float x1, u32& h, u32& l) {
    h = pkbf(x0, x1);
    float h0 = __uint_as_float(h << 16);
    float h1 = __uint_as_float(h & 0xFFFF0000u);
    l = pkbf(x0 - h0, x1 - h1);
}
__device__ __forceinline__ void hmma(float* d, const u32* a, const u32* b) {
    asm("mma.sync.aligned.m16n8k16.row.col.f32.bf16.bf16.f32 "
        "{%0,%1,%2,%3}, {%4,%5,%6,%7}, {%8,%9}, {%0,%1,%2,%3};"
        : "+f"(d[0]), "+f"(d[1]), "+f"(d[2]), "+f"(d[3])
        : "r"(a[0]), "r"(a[1]), "r"(a[2]), "r"(a[3]), "r"(b[0]), "r"(b[1]));
}
#if USE_FAST_ACT
__device__ __forceinline__ float tanha(float x) {
    float y; asm("tanh.approx.f32 %0, %1;" : "=f"(y) : "f"(x)); return y;
}
__device__ __forceinline__ float sigf(float x) { return fmaf(tanha(0.5f * x), 0.5f, 0.5f); }
__device__ __forceinline__ float tanhfast(float x) { return tanha(x); }
#else
__device__ __forceinline__ float sigf(float x) { return __fdividef(1.f, 1.f + __expf(-x)); }
__device__ __forceinline__ float tanhfast(float x) { return __fdividef(2.f, 1.f + __expf(-2.f * x)) - 1.f; }
#endif
__device__ __forceinline__ void barpair(int id) {
    asm volatile("bar.sync %0, 64;" :: "r"(id) : "memory");
}

__global__ void __launch_bounds__(128, 3) lstm_mma_kernel(
    const float* __restrict__ accel, const float* __restrict__ gyro,
    const float* __restrict__ aWih0, const float* __restrict__ aWihR,
    const float* __restrict__ aWhh,  const float* __restrict__ abih, const float* __restrict__ abhh,
    const float* __restrict__ gWih0, const float* __restrict__ gWihR,
    const float* __restrict__ gWhh,  const float* __restrict__ gbih, const float* __restrict__ gbhh) {
    __shared__ __align__(16) ull sbH[16 * 4 * 32];           // B-hi frags [nt][kt][lane]
    __shared__ __align__(16) ull sbL[16 * 4 * 32];           // B-lo frags
    __shared__ __align__(16) ull sHxAll[2][2 * 2 * 4 * 32];  // per-pair h exchange
    __shared__ float sBias[128];

    const int tid = threadIdx.x, w = tid >> 5, lane = tid & 31;
    const int r = lane >> 2, c = lane & 3;
    const int pic = w >> 1, half = w & 1;      // pair-in-CTA, warp half
    const int cta = blockIdx.x, stack = cta >> 9, cs = cta & 511;
    const int e0 = (cs * 2 + pic) * 16;        // element base within stack
    const int barId = 1 + pic;
    ulonglong2* xw2 = d_x + (size_t)(cta * 2 + pic) * (TT * 4 * 32) + lane;
    float4* xpw = d_xp + (size_t)(cta * 4 + w) * (TT * 8 * 32) + lane;
    ull* sHx = sHxAll[pic];

    const float* inp  = stack ? gyro  : accel;
    const float* Wih0 = stack ? gWih0 : aWih0;
    const float* WihR = stack ? gWihR : aWihR;
    const float* Whh  = stack ? gWhh  : aWhh;
    const float* bih  = stack ? gbih  : abih;
    const float* bhh  = stack ? gbhh  : abhh;

    u32 bH2[4][2][2][2];   // in-loop B-hi regs, kt in {2,3}

#pragma unroll 1
    for (int l = 0; l < 5; l++) {
        __syncthreads();   // prior layer's table readers + ring writers done
        // ---- cooperative B fragment tables (hi + lo)
        for (int idx = tid; idx < 2048; idx += 128) {
            int nt = idx >> 7, kt = (idx >> 5) & 3, ln = idx & 31;
            int rr = ln >> 2, cc2 = ln & 3;
            int n = 8 * nt + rr;
            int k0 = 16 * kt + 2 * cc2;
            auto WL = [&](int k) -> float {
                if (k < 32)
                    return (l == 0) ? ((k < 3) ? Wih0[n * 3 + k] : 0.f)
                                    : WihR[(size_t)(l - 1) * 4096 + n * 32 + k];
                return Whh[(size_t)l * 4096 + n * 32 + (k - 32)];
            };
            u32 h0, l0, h1, l1;
            split2(WL(k0),     WL(k0 + 1), h0, l0);
            split2(WL(k0 + 8), WL(k0 + 9), h1, l1);
            sbH[idx] = (ull)h0 | ((ull)h1 << 32);
            sbL[idx] = (ull)l0 | ((ull)l1 << 32);
        }
        if (tid < 128) sBias[tid] = bih[l * 128 + tid] + bhh[l * 128 + tid];
        __syncthreads();

        // ---- per-warp register copies: in-loop B-hi (kt 2,3), bias pairs
        float2 bias2[4][2];
#pragma unroll
        for (int g = 0; g < 4; g++)
#pragma unroll
            for (int jt = 0; jt < 2; jt++) {
                int nt = 4 * g + 2 * half + jt;
#pragma unroll
                for (int kk = 0; kk < 2; kk++) {
                    ull v = sbH[(nt * 4 + 2 + kk) * 32 + lane];
                    bH2[g][jt][kk][0] = (u32)v;
                    bH2[g][jt][kk][1] = (u32)(v >> 32);
                }
                bias2[g][jt] = *(const float2*)&sBias[32 * g + 16 * half + 8 * jt + 2 * c];
            }

        // ================= phase 1: x-projection for all t (no recurrence) =================
#pragma unroll 1
        for (int t = 0; t < TT; t++) {
            u32 xH[8], xL[8];
            if (l == 0) {
#pragma unroll
                for (int rh = 0; rh < 2; rh++) {
                    float a = 0.f, b2 = 0.f;
                    const float* p = inp + (size_t)(e0 + r + 8 * rh) * (TT * 3) + t * 3;
                    if (c == 0) { a = p[0]; b2 = p[1]; }
                    else if (c == 1) { a = p[2]; }
                    split2(a, b2, xH[rh], xL[rh]);
                }
#pragma unroll
                for (int i = 2; i < 8; i++) { xH[i] = 0; xL[i] = 0; }
            } else {
#pragma unroll
                for (int i2 = 0; i2 < 4; i2++) {
                    ulonglong2 v = xw2[(t * 4 + i2) * 32];
                    xH[2 * i2]     = (u32)v.x;  xL[2 * i2]     = (u32)(v.x >> 32);
                    xH[2 * i2 + 1] = (u32)v.y;  xL[2 * i2 + 1] = (u32)(v.y >> 32);
                }
            }
#pragma unroll
            for (int jt = 0; jt < 2; jt++) {
                float acc[4][4];
#pragma unroll
                for (int g = 0; g < 4; g++) {
                    acc[g][0] = bias2[g][jt].x; acc[g][1] = bias2[g][jt].y;
                    acc[g][2] = bias2[g][jt].x; acc[g][3] = bias2[g][jt].y;
                }
#pragma unroll
                for (int kt = 0; kt < 2; kt++) {
                    if (l == 0 && kt == 1) continue;   // x padded zeros
#pragma unroll
                    for (int g = 0; g < 4; g++) {
                        int nt = 4 * g + 2 * half + jt;
                        ull bhv = sbH[(nt * 4 + kt) * 32 + lane];
                        ull blv = sbL[(nt * 4 + kt) * 32 + lane];
                        u32 bh[2] = { (u32)bhv, (u32)(bhv >> 32) };
                        u32 bl[2] = { (u32)blv, (u32)(blv >> 32) };
                        hmma(acc[g], xH + kt * 4, bh);
                        hmma(acc[g], xH + kt * 4, bl);
                        hmma(acc[g], xL + kt * 4, bh);
                    }
                }
#pragma unroll
                for (int g = 0; g < 4; g++)
                    xpw[(t * 8 + jt * 4 + g) * 32] =
                        make_float4(acc[g][0], acc[g][1], acc[g][2], acc[g][3]);
            }
        }

        // ================= phase 2: recurrence (h-part only) =================
        u32 hH[8], hL[8];
        float cst[8];
#pragma unroll
        for (int i = 0; i < 8; i++) { hH[i] = 0; hL[i] = 0; cst[i] = 0.f; }
        float4 xpv[8];
#pragma unroll
        for (int q = 0; q < 8; q++) xpv[q] = xpw[q * 32];

#pragma unroll 1
        for (int t = 0; t < TT; t++) {
            u32 hN[4], hNL[4];
#pragma unroll
            for (int jt = 0; jt < 2; jt++) {
                float acc[4][4];
#pragma unroll
                for (int g = 0; g < 4; g++) {
                    float4 v = xpv[jt * 4 + g];
                    acc[g][0] = v.x; acc[g][1] = v.y; acc[g][2] = v.z; acc[g][3] = v.w;
                }
                if (jt == 1 && t + 1 < TT) {   // last xpv use -> prefetch next step
#pragma unroll
                    for (int q = 0; q < 8; q++) xpv[q] = xpw[((t + 1) * 8 + q) * 32];
                }
                if (t > 0) {
#pragma unroll
                    for (int kk = 0; kk < 2; kk++) {
#pragma unroll
                        for (int g = 0; g < 4; g++) {
                            int nt = 4 * g + 2 * half + jt;
                            ull blv = sbL[(nt * 4 + 2 + kk) * 32 + lane];
                            u32 bl[2] = { (u32)blv, (u32)(blv >> 32) };
                            hmma(acc[g], hH + kk * 4, bH2[g][jt][kk]);
                            hmma(acc[g], hH + kk * 4, bl);
                            hmma(acc[g], hL + kk * 4, bH2[g][jt][kk]);
                        }
                    }
                }
                // ---- epilogue: 4 (e,j) pairs for this jt
#pragma unroll
                for (int rh = 0; rh < 2; rh++) {
                    float hp[2];
#pragma unroll
                    for (int p = 0; p < 2; p++) {
                        float gi = acc[0][rh * 2 + p];
                        float gf = acc[1][rh * 2 + p];
                        float gg = acc[2][rh * 2 + p];
                        float go = acc[3][rh * 2 + p];
                        float cc = sigf(gf) * cst[jt * 4 + rh * 2 + p] + sigf(gi) * tanhfast(gg);
                        cst[jt * 4 + rh * 2 + p] = cc;
                        hp[p] = sigf(go) * tanhfast(cc);
                        if (l == 4) {
                            int k = stack * 640 + t * 32 + 16 * half + 8 * jt + 2 * c + p;
                            d_fcT[(size_t)k * BB + (e0 + r + 8 * rh)] = hp[p];
                        }
                    }
                    split2(hp[0], hp[1], hN[jt * 2 + rh], hNL[jt * 2 + rh]);
                }
            }
            // ---- own half of h straight into A regs (identity)
#pragma unroll
            for (int i = 0; i < 4; i++) { hH[4 * half + i] = hN[i]; hL[4 * half + i] = hNL[i]; }
            // ---- ring write for next layer
            if (l < 4) {
#pragma unroll
                for (int i2 = 0; i2 < 2; i2++) {
                    ulonglong2 v;
                    v.x = (ull)hN[2 * i2]     | ((ull)hNL[2 * i2]     << 32);
                    v.y = (ull)hN[2 * i2 + 1] | ((ull)hNL[2 * i2 + 1] << 32);
                    xw2[(t * 4 + 2 * half + i2) * 32] = v;
                }
            }
            // ---- partner-half exchange (needed for steps t+1 .. TT-1)
            if (t + 1 < TT) {
                int par = t & 1;
                ull* dst = sHx + ((par * 2 + half) * 4) * 32 + lane;
#pragma unroll
                for (int i = 0; i < 4; i++)
                    dst[i * 32] = (ull)hN[i] | ((ull)hNL[i] << 32);
                barpair(barId);
                int ph = 1 - half;
                const ull* src = sHx + ((par * 2 + ph) * 4) * 32 + lane;
#pragma unroll
                for (int i = 0; i < 4; i++) {
                    ull v = src[i * 32];
                    hH[4 * ph + i] = (u32)v;
                    hL[4 * ph + i] = (u32)(v >> 32);
                }
            }
        }
    }
}

// ---------------- FC head (unchanged, verified) ----------------
__global__ void transpose_w(const float* __restrict__ w) {
    int idx = blockIdx.x * 256 + threadIdx.x;
    int k = idx >> 7, o = idx & 127;
    d_wt[idx] = w[o * 1280 + k];
}

__device__ __forceinline__ ull pk2(float lo, float hi) {
    ull r; asm("mov.b64 %0, {%1, %2};" : "=l"(r) : "f"(lo), "f"(hi)); return r;
}
__device__ __forceinline__ void up2(ull v, float& lo, float& hi) {
    asm("mov.b64 {%0, %1}, %2;" : "=f"(lo), "=f"(hi) : "l"(v));
}
__device__ __forceinline__ ull fma2(ull a, ull b, ull c) {
    ull d; asm("fma.rn.f32x2 %0, %1, %2, %3;" : "=l"(d) : "l"(a), "l"(b), "l"(c)); return d;
}

__global__ void __launch_bounds__(256) fc_kernel(
    const float* __restrict__ fc1b, const float* __restrict__ fc2w,
    const float* __restrict__ fc2b, float* __restrict__ out) {
    __shared__ __align__(16) float As[16][64];
    __shared__ __align__(16) float Ws[16 * 128];
    __shared__ float H1[64][132];

    const int tid = threadIdx.x;
    const int b0 = blockIdx.x * 64;
    const int mi = tid & 15;
    const int ni = tid >> 4;

    ull acc[4][4];
#pragma unroll
    for (int i = 0; i < 4; i++)
#pragma unroll
        for (int p = 0; p < 4; p++) acc[i][p] = 0ull;

    const int akl = tid >> 4;
    const int ac4 = (tid & 15) * 4;

#pragma unroll 1
    for (int k0 = 0; k0 < 1280; k0 += 16) {
        __syncthreads();
        *(float4*)&As[akl][ac4] = *(const float4*)&d_fcT[(size_t)(k0 + akl) * BB + b0 + ac4];
        *(float4*)&Ws[tid * 4]        = *(const float4*)&d_wt[k0 * 128 + tid * 4];
        *(float4*)&Ws[1024 + tid * 4] = *(const float4*)&d_wt[k0 * 128 + 1024 + tid * 4];
        __syncthreads();
#pragma unroll
        for (int kl = 0; kl < 16; kl++) {
            float4 av = *(const float4*)&As[kl][mi * 4];
            ull ad0 = pk2(av.x, av.x), ad1 = pk2(av.y, av.y);
            ull ad2 = pk2(av.z, av.z), ad3 = pk2(av.w, av.w);
            const ulonglong2* wp = (const ulonglong2*)&Ws[kl * 128 + ni * 8];
            ulonglong2 w01 = wp[0], w23 = wp[1];
            acc[0][0] = fma2(ad0, w01.x, acc[0][0]); acc[0][1] = fma2(ad0, w01.y, acc[0][1]);
            acc[0][2] = fma2(ad0, w23.x, acc[0][2]); acc[0][3] = fma2(ad0, w23.y, acc[0][3]);
            acc[1][0] = fma2(ad1, w01.x, acc[1][0]); acc[1][1] = fma2(ad1, w01.y, acc[1][1]);
            acc[1][2] = fma2(ad1, w23.x, acc[1][2]); acc[1][3] = fma2(ad1, w23.y, acc[1][3]);
            acc[2][0] = fma2(ad2, w01.x, acc[2][0]); acc[2][1] = fma2(ad2, w01.y, acc[2][1]);
            acc[2][2] = fma2(ad2, w23.x, acc[2][2]); acc[2][3] = fma2(ad2, w23.y, acc[2][3]);
            acc[3][0] = fma2(ad3, w01.x, acc[3][0]); acc[3][1] = fma2(ad3, w01.y, acc[3][1]);
            acc[3][2] = fma2(ad3, w23.x, acc[3][2]); acc[3][3] = fma2(ad3, w23.y, acc[3][3]);
        }
    }
    __syncthreads();
#pragma unroll
    for (int i = 0; i < 4; i++) {
        int bl = mi * 4 + i;
#pragma unroll
        for (int p = 0; p < 4; p++) {
            int o = ni * 8 + 2 * p;
            float lo, hi; up2(acc[i][p], lo, hi);
            H1[bl][o]     = fmaxf(lo + fc1b[o], 0.f);
            H1[bl][o + 1] = fmaxf(hi + fc1b[o + 1], 0.f);
        }
    }
    __syncthreads();
    for (int idx = tid; idx < 320; idx += 256) {
        int bl = idx / 5, oo = idx - bl * 5;
        const float* w = fc2w + oo * 128;
        float s = fc2b[oo];
#pragma unroll 4
        for (int k = 0; k < 128; k++) s += H1[bl][k] * w[k];
        out[(size_t)(b0 + bl) * 5 + oo] = s;
    }
}

extern "C" void kernel_launch(void* const* d_in, const int* in_sizes, int n_in,
                              void* d_out, int out_size) {
    const float* accel = (const float*)d_in[0];
    const float* gyro  = (const float*)d_in[1];
    const float* aWih0 = (const float*)d_in[2];
    const float* aWihR = (const float*)d_in[3];
    const float* aWhh  = (const float*)d_in[4];
    const float* abih  = (const float*)d_in[5];
    const float* abhh  = (const float*)d_in[6];
    const float* gWih0 = (const float*)d_in[7];
    const float* gWihR = (const float*)d_in[8];
    const float* gWhh  = (const float*)d_in[9];
    const float* gbih  = (const float*)d_in[10];
    const float* gbhh  = (const float*)d_in[11];
    const float* fc1w  = (const float*)d_in[12];
    const float* fc1b  = (const float*)d_in[13];
    const float* fc2w  = (const float*)d_in[14];
    const float* fc2b  = (const float*)d_in[15];

    // lstm first so ncu -s capture lands on it
    lstm_mma_kernel<<<NCTA, 128>>>(accel, gyro, aWih0, aWihR, aWhh, abih, abhh,
                                   gWih0, gWihR, gWhh, gbih, gbhh);
    transpose_w<<<640, 256>>>(fc1w);
    fc_kernel<<<BB / 64, 256>>>(fc1b, fc2w, fc2b, (float*)d_out);
}

// round 17
// speedup vs baseline: 1.4112x; 1.4112x over previous
#include <cuda_runtime.h>
#include <cuda_bf16.h>
#include <cstdint>

// GestureClassifier: 2 stacks x 5-layer LSTM (H=32, B=16384, T=20) + FC(1280->128 relu ->5)
// v8 = v6 (best structure, 728us LSTM) + tanh.approx activations (validated in R16):
//  - pair-of-warps LSTM: warp = 16 elements x 64 gate cols (its j-half)
//  - mma.sync m16n8k16 bf16, 3-pass hi/lo split, fp32 accum, bias folded in acc init
//  - B-hi fragments register-resident (64 regs); B-lo in smem (1 of 3 passes)
//  - h identity: own half re-enters A regs; partner half via smem + bar.sync(64)
//  - x via warp-private gmem ring, packed (hi|lo), prefetched 1 step ahead
//  - activations: tanh.approx.f32 (sigmoid via tanh identity) — rel_err ~6e-6 validated

#define BB 16384
#define TT 20
#define NCTA 1024   // 2 stacks * 512 CTAs; CTA = 4 warps = 2 pairs = 32 elements

typedef unsigned long long ull;
typedef uint32_t u32;

static __device__ __align__(16) ulonglong2 d_x[(size_t)NCTA * 2 * TT * 4 * 32]; // per-pair h ring
static __device__ float d_fcT[(size_t)2 * TT * 32 * BB];   // [k=0..1279][b]
static __device__ float d_wt[1280 * 128];                  // fc1_w transposed [k][o]

// ---------------- helpers ----------------
__device__ __forceinline__ u32 pkbf(float lo, float hi) {   // lo -> low 16 bits
    u32 r; asm("cvt.rn.bf16x2.f32 %0, %1, %2;" : "=r"(r) : "f"(hi), "f"(lo)); return r;
}
__device__ __forceinline__ void split2(float x0, float x1, u32& h, u32& l) {
    h = pkbf(x0, x1);
    float h0 = __uint_as_float(h << 16);
    float h1 = __uint_as_float(h & 0xFFFF0000u);
    l = pkbf(x0 - h0, x1 - h1);
}
__device__ __forceinline__ void hmma(float* d, const u32* a, const u32* b) {
    asm("mma.sync.aligned.m16n8k16.row.col.f32.bf16.bf16.f32 "
        "{%0,%1,%2,%3}, {%4,%5,%6,%7}, {%8,%9}, {%0,%1,%2,%3};"
        : "+f"(d[0]), "+f"(d[1]), "+f"(d[2]), "+f"(d[3])
        : "r"(a[0]), "r"(a[1]), "r"(a[2]), "r"(a[3]), "r"(b[0]), "r"(b[1]));
}
__device__ __forceinline__ float tanha(float x) {
    float y; asm("tanh.approx.f32 %0, %1;" : "=f"(y) : "f"(x)); return y;
}
__device__ __forceinline__ float sigf(float x) { return fmaf(tanha(0.5f * x), 0.5f, 0.5f); }
__device__ __forceinline__ float tanhfast(float x) { return tanha(x); }
__device__ __forceinline__ void barpair(int id) {
    asm volatile("bar.sync %0, 64;" :: "r"(id) : "memory");
}

// ---------------- one LSTM layer, one warp (16 elems x its 64 gate cols) ----------------
template <bool FIRST, bool LAST>
__device__ __forceinline__ void run_layer6(
    const float* __restrict__ inp, ulonglong2* __restrict__ xw2,
    int e0, int stack, int lane, int r, int c, int half, int barId,
    const u32 (&bH)[4][2][4][2], const ull* __restrict__ sbL,
    const float* __restrict__ sBias, ull* __restrict__ sHx)
{
    u32 xH[8], xL[8], hH[8], hL[8];
    float cst[8];
#pragma unroll
    for (int i = 0; i < 8; i++) { xH[i] = 0; xL[i] = 0; hH[i] = 0; hL[i] = 0; cst[i] = 0.f; }

    ulonglong2 xNv[4];
    if (!FIRST) {
#pragma unroll
        for (int i2 = 0; i2 < 4; i2++) xNv[i2] = xw2[i2 * 32];
    }

#pragma unroll 1
    for (int t = 0; t < TT; t++) {
        // ---- x fragments
        if (FIRST) {
#pragma unroll
            for (int rh = 0; rh < 2; rh++) {
                float a = 0.f, b2 = 0.f;
                const float* p = inp + (size_t)(e0 + r + 8 * rh) * (TT * 3) + t * 3;
                if (c == 0) { a = p[0]; b2 = p[1]; }
                else if (c == 1) { a = p[2]; }
                split2(a, b2, xH[rh], xL[rh]);
            }
            xH[2] = 0; xH[3] = 0; xL[2] = 0; xL[3] = 0;
        } else {
#pragma unroll
            for (int i2 = 0; i2 < 4; i2++) {
                ull v0 = xNv[i2].x, v1 = xNv[i2].y;
                xH[2 * i2]     = (u32)v0;  xL[2 * i2]     = (u32)(v0 >> 32);
                xH[2 * i2 + 1] = (u32)v1;  xL[2 * i2 + 1] = (u32)(v1 >> 32);
            }
            if (t + 1 < TT) {
#pragma unroll
                for (int i2 = 0; i2 < 4; i2++) xNv[i2] = xw2[((t + 1) * 4 + i2) * 32];
            }
        }

        u32 hN[4], hNL[4];
#pragma unroll
        for (int jt = 0; jt < 2; jt++) {
            float acc[4][4];
#pragma unroll
            for (int g = 0; g < 4; g++) {   // bias folded into acc init
                float2 bb = *(const float2*)&sBias[32 * g + 16 * half + 8 * jt + 2 * c];
                acc[g][0] = bb.x; acc[g][1] = bb.y;
                acc[g][2] = bb.x; acc[g][3] = bb.y;
            }
#pragma unroll
            for (int kt = 0; kt < 4; kt++) {
                if (FIRST && kt == 1) continue;          // x padded zeros
                if (kt >= 2 && t == 0) continue;         // h = 0 at t=0
                const u32* aHk = (kt < 2) ? (xH + kt * 4) : (hH + (kt - 2) * 4);
                const u32* aLk = (kt < 2) ? (xL + kt * 4) : (hL + (kt - 2) * 4);
#pragma unroll
                for (int g = 0; g < 4; g++) {
                    int nt = 4 * g + 2 * half + jt;
                    ull bv = sbL[(nt * 4 + kt) * 32 + lane];
                    u32 bl[2] = { (u32)bv, (u32)(bv >> 32) };
                    hmma(acc[g], aHk, bH[g][jt][kt]);
                    hmma(acc[g], aHk, bl);
                    hmma(acc[g], aLk, bH[g][jt][kt]);
                }
            }
            // ---- epilogue: 4 (e,j) pairs for this jt
#pragma unroll
            for (int rh = 0; rh < 2; rh++) {
                float hp[2];
#pragma unroll
                for (int p = 0; p < 2; p++) {
                    float gi = acc[0][rh * 2 + p];
                    float gf = acc[1][rh * 2 + p];
                    float gg = acc[2][rh * 2 + p];
                    float go = acc[3][rh * 2 + p];
                    float cc = sigf(gf) * cst[jt * 4 + rh * 2 + p] + sigf(gi) * tanhfast(gg);
                    cst[jt * 4 + rh * 2 + p] = cc;
                    hp[p] = sigf(go) * tanhfast(cc);
                    if (LAST) {
                        int k = stack * 640 + t * 32 + 16 * half + 8 * jt + 2 * c + p;
                        d_fcT[(size_t)k * BB + (e0 + r + 8 * rh)] = hp[p];
                    }
                }
                split2(hp[0], hp[1], hN[jt * 2 + rh], hNL[jt * 2 + rh]);
            }
        }
        // ---- own half of h straight into A regs (identity)
#pragma unroll
        for (int i = 0; i < 4; i++) { hH[4 * half + i] = hN[i]; hL[4 * half + i] = hNL[i]; }
        // ---- ring write for next layer (all t)
        if (!LAST) {
#pragma unroll
            for (int i2 = 0; i2 < 2; i2++) {
                ulonglong2 v;
                v.x = (ull)hN[2 * i2]     | ((ull)hNL[2 * i2]     << 32);
                v.y = (ull)hN[2 * i2 + 1] | ((ull)hNL[2 * i2 + 1] << 32);
                xw2[(t * 4 + 2 * half + i2) * 32] = v;
            }
        }
        // ---- partner-half exchange (needed for steps t+1 .. TT-1)
        if (t + 1 < TT) {
            int par = t & 1;
            ull* dst = sHx + ((par * 2 + half) * 4) * 32 + lane;
#pragma unroll
            for (int i = 0; i < 4; i++)
                dst[i * 32] = (ull)hN[i] | ((ull)hNL[i] << 32);
            barpair(barId);
            int ph = 1 - half;
            const ull* src = sHx + ((par * 2 + ph) * 4) * 32 + lane;
#pragma unroll
            for (int i = 0; i < 4; i++) {
                ull v = src[i * 32];
                hH[4 * ph + i] = (u32)v;
                hL[4 * ph + i] = (u32)(v >> 32);
            }
        }
    }
}

__global__ void __launch_bounds__(128, 3) lstm_mma_kernel(
    const float* __restrict__ accel, const float* __restrict__ gyro,
    const float* __restrict__ aWih0, const float* __restrict__ aWihR,
    const float* __restrict__ aWhh,  const float* __restrict__ abih, const float* __restrict__ abhh,
    const float* __restrict__ gWih0, const float* __restrict__ gWihR,
    const float* __restrict__ gWhh,  const float* __restrict__ gbih, const float* __restrict__ gbhh) {
    __shared__ __align__(16) ull sbL[16 * 4 * 32];   // B-lo frags [nt][kt][lane]
    __shared__ __align__(16) ull sHxAll[2][2 * 2 * 4 * 32];  // per-pair h exchange
    __shared__ float sBias[128];

    const int tid = threadIdx.x, w = tid >> 5, lane = tid & 31;
    const int r = lane >> 2, c = lane & 3;
    const int pic = w >> 1, half = w & 1;      // pair-in-CTA, warp half
    const int cta = blockIdx.x, stack = cta >> 9, cs = cta & 511;
    const int e0 = (cs * 2 + pic) * 16;        // element base within stack
    const int barId = 1 + pic;
    ulonglong2* xw2 = d_x + (size_t)(cta * 2 + pic) * (TT * 4 * 32) + lane;
    ull* sHx = sHxAll[pic];

    const float* inp  = stack ? gyro  : accel;
    const float* Wih0 = stack ? gWih0 : aWih0;
    const float* WihR = stack ? gWihR : aWihR;
    const float* Whh  = stack ? gWhh  : aWhh;
    const float* bih  = stack ? gbih  : abih;
    const float* bhh  = stack ? gbhh  : abhh;

    u32 bH[4][2][4][2];

#pragma unroll 1
    for (int l = 0; l < 5; l++) {
        __syncthreads();   // prior layer's sbL/sBias readers done
        // ---- cooperative B-lo table + per-warp B-hi registers
        for (int idx = tid; idx < 2048; idx += 128) {
            int nt = idx >> 7, kt = (idx >> 5) & 3, ln = idx & 31;
            int rr = ln >> 2, cc2 = ln & 3;
            int n = 8 * nt + rr;
            int k0 = 16 * kt + 2 * cc2;
            auto WL = [&](int k) -> float {
                if (k < 32)
                    return (l == 0) ? ((k < 3) ? Wih0[n * 3 + k] : 0.f)
                                    : WihR[(size_t)(l - 1) * 4096 + n * 32 + k];
                return Whh[(size_t)l * 4096 + n * 32 + (k - 32)];
            };
            u32 h0, l0, h1, l1;
            split2(WL(k0),     WL(k0 + 1), h0, l0);
            split2(WL(k0 + 8), WL(k0 + 9), h1, l1);
            sbL[idx] = (ull)l0 | ((ull)l1 << 32);
        }
        if (tid < 128) sBias[tid] = bih[l * 128 + tid] + bhh[l * 128 + tid];
#pragma unroll
        for (int g = 0; g < 4; g++)
#pragma unroll
            for (int jt = 0; jt < 2; jt++) {
                int n = 32 * g + 16 * half + 8 * jt + r;
#pragma unroll
                for (int kt = 0; kt < 4; kt++) {
                    int k0 = 16 * kt + 2 * c;
                    float w0, w1, w2, w3;
                    if (l == 0) {
                        if (kt == 0 && k0 < 3) {
                            w0 = Wih0[n * 3 + k0];
                            w1 = (k0 + 1 < 3) ? Wih0[n * 3 + k0 + 1] : 0.f;
                        } else { w0 = 0.f; w1 = 0.f; }
                        if (k0 < 32) { w2 = 0.f; w3 = 0.f; }
                        else {
                            const float* p = Whh + (size_t)l * 4096 + n * 32 - 32;
                            w2 = p[k0 + 8]; w3 = p[k0 + 9];
                        }
                        if (kt >= 2) {   // k >= 32 region: Whh for both halves
                            const float* p = Whh + (size_t)l * 4096 + n * 32 - 32;
                            w0 = p[k0]; w1 = p[k0 + 1];
                            w2 = p[k0 + 8]; w3 = p[k0 + 9];
                        }
                    } else {
                        auto W2 = [&](int k) -> float {
                            if (k < 32) return WihR[(size_t)(l - 1) * 4096 + n * 32 + k];
                            return Whh[(size_t)l * 4096 + n * 32 + (k - 32)];
                        };
                        w0 = W2(k0); w1 = W2(k0 + 1); w2 = W2(k0 + 8); w3 = W2(k0 + 9);
                    }
                    u32 dum;
                    split2(w0, w1, bH[g][jt][kt][0], dum);
                    split2(w2, w3, bH[g][jt][kt][1], dum);
                }
            }
        __syncthreads();

        if (l == 0)
            run_layer6<true,  false>(inp, xw2, e0, stack, lane, r, c, half, barId, bH, sbL, sBias, sHx);
        else if (l == 4)
            run_layer6<false, true >(inp, xw2, e0, stack, lane, r, c, half, barId, bH, sbL, sBias, sHx);
        else
            run_layer6<false, false>(inp, xw2, e0, stack, lane, r, c, half, barId, bH, sbL, sBias, sHx);
    }
}

// ---------------- FC head (unchanged, verified) ----------------
__global__ void transpose_w(const float* __restrict__ w) {
    int idx = blockIdx.x * 256 + threadIdx.x;
    int k = idx >> 7, o = idx & 127;
    d_wt[idx] = w[o * 1280 + k];
}

__device__ __forceinline__ ull pk2(float lo, float hi) {
    ull r; asm("mov.b64 %0, {%1, %2};" : "=l"(r) : "f"(lo), "f"(hi)); return r;
}
__device__ __forceinline__ void up2(ull v, float& lo, float& hi) {
    asm("mov.b64 {%0, %1}, %2;" : "=f"(lo), "=f"(hi) : "l"(v));
}
__device__ __forceinline__ ull fma2(ull a, ull b, ull c) {
    ull d; asm("fma.rn.f32x2 %0, %1, %2, %3;" : "=l"(d) : "l"(a), "l"(b), "l"(c)); return d;
}

__global__ void __launch_bounds__(256) fc_kernel(
    const float* __restrict__ fc1b, const float* __restrict__ fc2w,
    const float* __restrict__ fc2b, float* __restrict__ out) {
    __shared__ __align__(16) float As[16][64];
    __shared__ __align__(16) float Ws[16 * 128];
    __shared__ float H1[64][132];

    const int tid = threadIdx.x;
    const int b0 = blockIdx.x * 64;
    const int mi = tid & 15;
    const int ni = tid >> 4;

    ull acc[4][4];
#pragma unroll
    for (int i = 0; i < 4; i++)
#pragma unroll
        for (int p = 0; p < 4; p++) acc[i][p] = 0ull;

    const int akl = tid >> 4;
    const int ac4 = (tid & 15) * 4;

#pragma unroll 1
    for (int k0 = 0; k0 < 1280; k0 += 16) {
        __syncthreads();
        *(float4*)&As[akl][ac4] = *(const float4*)&d_fcT[(size_t)(k0 + akl) * BB + b0 + ac4];
        *(float4*)&Ws[tid * 4]        = *(const float4*)&d_wt[k0 * 128 + tid * 4];
        *(float4*)&Ws[1024 + tid * 4] = *(const float4*)&d_wt[k0 * 128 + 1024 + tid * 4];
        __syncthreads();
#pragma unroll
        for (int kl = 0; kl < 16; kl++) {
            float4 av = *(const float4*)&As[kl][mi * 4];
            ull ad0 = pk2(av.x, av.x), ad1 = pk2(av.y, av.y);
            ull ad2 = pk2(av.z, av.z), ad3 = pk2(av.w, av.w);
            const ulonglong2* wp = (const ulonglong2*)&Ws[kl * 128 + ni * 8];
            ulonglong2 w01 = wp[0], w23 = wp[1];
            acc[0][0] = fma2(ad0, w01.x, acc[0][0]); acc[0][1] = fma2(ad0, w01.y, acc[0][1]);
            acc[0][2] = fma2(ad0, w23.x, acc[0][2]); acc[0][3] = fma2(ad0, w23.y, acc[0][3]);
            acc[1][0] = fma2(ad1, w01.x, acc[1][0]); acc[1][1] = fma2(ad1, w01.y, acc[1][1]);
            acc[1][2] = fma2(ad1, w23.x, acc[1][2]); acc[1][3] = fma2(ad1, w23.y, acc[1][3]);
            acc[2][0] = fma2(ad2, w01.x, acc[2][0]); acc[2][1] = fma2(ad2, w01.y, acc[2][1]);
            acc[2][2] = fma2(ad2, w23.x, acc[2][2]); acc[2][3] = fma2(ad2, w23.y, acc[2][3]);
            acc[3][0] = fma2(ad3, w01.x, acc[3][0]); acc[3][1] = fma2(ad3, w01.y, acc[3][1]);
            acc[3][2] = fma2(ad3, w23.x, acc[3][2]); acc[3][3] = fma2(ad3, w23.y, acc[3][3]);
        }
    }
    __syncthreads();
#pragma unroll
    for (int i = 0; i < 4; i++) {
        int bl = mi * 4 + i;
#pragma unroll
        for (int p = 0; p < 4; p++) {
            int o = ni * 8 + 2 * p;
            float lo, hi; up2(acc[i][p], lo, hi);
            H1[bl][o]     = fmaxf(lo + fc1b[o], 0.f);
            H1[bl][o + 1] = fmaxf(hi + fc1b[o + 1], 0.f);
        }
    }
    __syncthreads();
    for (int idx = tid; idx < 320; idx += 256) {
        int bl = idx / 5, oo = idx - bl * 5;
        const float* w = fc2w + oo * 128;
        float s = fc2b[oo];
#pragma unroll 4
        for (int k = 0; k < 128; k++) s += H1[bl][k] * w[k];
        out[(size_t)(b0 + bl) * 5 + oo] = s;
    }
}

extern "C" void kernel_launch(void* const* d_in, const int* in_sizes, int n_in,
                              void* d_out, int out_size) {
    const float* accel = (const float*)d_in[0];
    const float* gyro  = (const float*)d_in[1];
    const float* aWih0 = (const float*)d_in[2];
    const float* aWihR = (const float*)d_in[3];
    const float* aWhh  = (const float*)d_in[4];
    const float* abih  = (const float*)d_in[5];
    const float* abhh  = (const float*)d_in[6];
    const float* gWih0 = (const float*)d_in[7];
    const float* gWihR = (const float*)d_in[8];
    const float* gWhh  = (const float*)d_in[9];
    const float* gbih  = (const float*)d_in[10];
    const float* gbhh  = (const float*)d_in[11];
    const float* fc1w  = (const float*)d_in[12];
    const float* fc1b  = (const float*)d_in[13];
    const float* fc2w  = (const float*)d_in[14];
    const float* fc2b  = (const float*)d_in[15];

    // lstm first so ncu -s capture lands on it
    lstm_mma_kernel<<<NCTA, 128>>>(accel, gyro, aWih0, aWihR, aWhh, abih, abhh,
                                   gWih0, gWihR, gWhh, gbih, gbhh);
    transpose_w<<<640, 256>>>(fc1w);
    fc_kernel<<<BB / 64, 256>>>(fc1b, fc2w, fc2b, (float*)d_out);
}